// round 4
// baseline (speedup 1.0000x reference)
#include <cuda_runtime.h>
#include <cstdint>

// path[row][t] = 0.3 + (lam0[row] - 0.3) * 0.5^t   (closed form of the scan;
// clamp inactive after step 0; 0.5^t exact power of two via exponent bits).
//
// R4: R2's store config (plain STG.128, no streaming hint -- __stcs regressed
// kernel time in R3) + R3's hoisted loop-invariant decay factors + exact
// divisibility: GRID*BLOCK = 524288 divides n4 = 2^23, so every thread runs
// EXACTLY 16 iterations -> fully unrolled, no tail predicates, 16 independent
// STG.128 in flight per thread.

static constexpr int HORIZON = 256;
static constexpr int T4_PER_ROW = HORIZON / 4;       // 64 float4 per row
static constexpr unsigned GRID = 2048;
static constexpr unsigned BLOCK = 256;
static constexpr unsigned STRIDE = GRID * BLOCK;     // 524288 = 2^19, multiple of 64
static constexpr unsigned N4 = 131072u * T4_PER_ROW; // 2^23 float4 total
static constexpr int ITERS = N4 / STRIDE;            // exactly 16

__global__ __launch_bounds__(BLOCK) void lyap_path_kernel(
    const float* __restrict__ lam0, float* __restrict__ out)
{
    unsigned idx4 = blockIdx.x * BLOCK + threadIdx.x;

    // Loop-invariant: t = 4 * (idx4 % 64) is fixed per thread (STRIDE % 64 == 0).
    int t = (int)(idx4 & (T4_PER_ROW - 1)) << 2;
    int e = 127 - t;
    const float f0 = (e > 0) ? __uint_as_float((unsigned)e << 23) : 0.0f;
    const float f1 = f0 * 0.5f;
    const float f2 = f1 * 0.5f;
    const float f3 = f2 * 0.5f;

    float4* __restrict__ out4 = reinterpret_cast<float4*>(out);
    const unsigned row_stride = STRIDE / T4_PER_ROW;  // 8192
    unsigned row = idx4 >> 6;

    #pragma unroll
    for (int i = 0; i < ITERS; i++, idx4 += STRIDE, row += row_stride) {
        float diff = __ldg(&lam0[row]) - 0.3f;

        float4 v;
        v.x = fmaf(diff, f0, 0.3f);
        v.y = fmaf(diff, f1, 0.3f);
        v.z = fmaf(diff, f2, 0.3f);
        v.w = fmaf(diff, f3, 0.3f);

        out4[idx4] = v;
    }
}

extern "C" void kernel_launch(void* const* d_in, const int* in_sizes, int n_in,
                              void* d_out, int out_size)
{
    const float* lam0 = (const float*)d_in[0];
    float* out = (float*)d_out;

    lyap_path_kernel<<<GRID, BLOCK>>>(lam0, out);
}

// round 6
// speedup vs baseline: 1.0510x; 1.0510x over previous
#include <cuda_runtime.h>
#include <cstdint>

// path[row][t] = 0.3 + (lam0[row] - 0.3) * 0.5^t   (closed form of the scan;
// clamp inactive after step 0; 0.5^t exact power of two via exponent bits).
//
// R5 (resubmit after broker timeout): R4's loop structure (exact 16
// iterations, hoisted loop-invariant decay factors, grid*block = 2^19 divides
// n4 = 2^23) + __stcs streaming stores.
// Rationale: ncu's single-launch time favors plain stores (writeback deferred
// past measurement), but the timed bench replays the graph back-to-back --
// in steady state 134 MB/iter must reach DRAM, and evict-first overlaps that
// writeback with the next iteration's store stream (R3 bench 24.64 vs R2/R4
// plain-store 25.98/25.06). Optimize the bench metric, not the ncu artifact.

static constexpr int HORIZON = 256;
static constexpr int T4_PER_ROW = HORIZON / 4;       // 64 float4 per row
static constexpr unsigned GRID = 2048;
static constexpr unsigned BLOCK = 256;
static constexpr unsigned STRIDE = GRID * BLOCK;     // 524288 = 2^19, multiple of 64
static constexpr unsigned N4 = 131072u * T4_PER_ROW; // 2^23 float4 total
static constexpr int ITERS = N4 / STRIDE;            // exactly 16

__global__ __launch_bounds__(BLOCK) void lyap_path_kernel(
    const float* __restrict__ lam0, float* __restrict__ out)
{
    unsigned idx4 = blockIdx.x * BLOCK + threadIdx.x;

    // Loop-invariant: t = 4 * (idx4 % 64) is fixed per thread (STRIDE % 64 == 0).
    int t = (int)(idx4 & (T4_PER_ROW - 1)) << 2;
    int e = 127 - t;
    const float f0 = (e > 0) ? __uint_as_float((unsigned)e << 23) : 0.0f;
    const float f1 = f0 * 0.5f;
    const float f2 = f1 * 0.5f;
    const float f3 = f2 * 0.5f;

    float4* __restrict__ out4 = reinterpret_cast<float4*>(out);
    const unsigned row_stride = STRIDE / T4_PER_ROW;  // 8192
    unsigned row = idx4 >> 6;

    #pragma unroll
    for (int i = 0; i < ITERS; i++, idx4 += STRIDE, row += row_stride) {
        float diff = __ldg(&lam0[row]) - 0.3f;

        float4 v;
        v.x = fmaf(diff, f0, 0.3f);
        v.y = fmaf(diff, f1, 0.3f);
        v.z = fmaf(diff, f2, 0.3f);
        v.w = fmaf(diff, f3, 0.3f);

        __stcs(&out4[idx4], v);   // evict-first: overlap writeback with next replay
    }
}

extern "C" void kernel_launch(void* const* d_in, const int* in_sizes, int n_in,
                              void* d_out, int out_size)
{
    const float* lam0 = (const float*)d_in[0];
    float* out = (float*)d_out;

    lyap_path_kernel<<<GRID, BLOCK>>>(lam0, out);
}